// round 1
// baseline (speedup 1.0000x reference)
#include <cuda_runtime.h>

#define B_VAL 16
#define M_VAL 64
#define A_VAL 33600
#define BM_VAL (B_VAL * M_VAL)
#define BA_VAL (B_VAL * A_VAL)
#define NC 80
#define EPSV 1e-9f

// Scratch: per-(b,anchor) positive count and (one) contributing gt index.
__device__ int g_pos_count[BA_VAL];
__device__ int g_pos_gt[BA_VAL];

// ---------------------------------------------------------------------------
// Anchor geometry is analytic (exact in f32): level strides 8/16/32,
// grid sides 160/80/40, half-extent 2.5*s.
// ---------------------------------------------------------------------------
__device__ __forceinline__ void anchor_geom(int a, float& cx, float& cy, float& half) {
    int base, nside; float s;
    if (a < 25600)      { s = 8.f;  base = 0;     nside = 160; }
    else if (a < 32000) { s = 16.f; base = 25600; nside = 80;  }
    else                { s = 32.f; base = 32000; nside = 40;  }
    int loc = a - base;
    cx = ((loc % nside) + 0.5f) * s;
    cy = ((loc / nside) + 0.5f) * s;
    half = 2.5f * s;
}

__device__ __forceinline__ float iou_eval(float ax0, float ay0, float ax1, float ay1,
                                          float area_a,
                                          float gx0, float gy0, float gx1, float gy1) {
    float area_g = (gx1 - gx0) * (gy1 - gy0);
    float lx = fmaxf(gx0, ax0), ly = fmaxf(gy0, ay0);
    float rx = fminf(gx1, ax1), ry = fminf(gy1, ay1);
    float w = fmaxf(rx - lx, 0.f), h = fmaxf(ry - ly, 0.f);
    float ov = w * h;
    return ov / (area_g + area_a - ov + EPSV);
}

// ---------------------------------------------------------------------------
// Kernel 0: zero the scatter tables (must happen every launch: graph replays).
// ---------------------------------------------------------------------------
__global__ void zero_kernel() {
    int i = blockIdx.x * blockDim.x + threadIdx.x;
    if (i < BA_VAL) g_pos_count[i] = 0;
}

// ---------------------------------------------------------------------------
// Kernel 1: one block per (b, m). For each of 3 levels, find the 9 anchors
// with the smallest center distance (squared distance: same order), then
// compute iou for the 27 candidates, threshold = mean + std(ddof=1), test
// center-inside-gt, and atomically scatter positives into g_pos_*.
// ---------------------------------------------------------------------------
__global__ void __launch_bounds__(256) topk_assign_kernel(const float* __restrict__ gt_bboxes,
                                                          const float* __restrict__ pad_mask) {
    const int blk = blockIdx.x;           // b*64 + m
    const int b = blk >> 6;
    const int m = blk & 63;
    if (pad_mask[blk] <= 0.f) return;     // invalid gt contributes nothing

    const float4 g = reinterpret_cast<const float4*>(gt_bboxes)[blk];
    const float gx0 = g.x, gy0 = g.y, gx1 = g.z, gy1 = g.w;
    const float gcx = (gx0 + gx1) * 0.5f, gcy = (gy0 + gy1) * 0.5f;

    __shared__ float Pd[256 * 9], Qd[256 * 9];
    __shared__ int   Pi[256 * 9], Qi[256 * 9];
    __shared__ int   topk_i[27];
    __shared__ float iou_s[27];
    __shared__ int   ok_s[27];
    __shared__ float thr_s;

    const int tid = threadIdx.x;

#pragma unroll
    for (int lvl = 0; lvl < 3; lvl++) {
        const int   base  = (lvl == 0) ? 0     : (lvl == 1) ? 25600 : 32000;
        const int   n     = (lvl == 0) ? 25600 : (lvl == 1) ? 6400  : 1600;
        const int   nside = (lvl == 0) ? 160   : (lvl == 1) ? 80    : 40;
        const float s     = (lvl == 0) ? 8.f   : (lvl == 1) ? 16.f  : 32.f;

        // thread-local sorted top-9 (ascending d2)
        float bd[9]; int bi[9];
#pragma unroll
        for (int k = 0; k < 9; k++) { bd[k] = 3.4e38f; bi[k] = 0; }

        for (int j = tid; j < n; j += 256) {
            float cx = ((j % nside) + 0.5f) * s;
            float cy = ((j / nside) + 0.5f) * s;
            float dx = gcx - cx, dy = gcy - cy;
            float d2 = dx * dx + dy * dy;
            if (d2 < bd[8]) {
                float v = d2; int vi = base + j;
#pragma unroll
                for (int k = 0; k < 9; k++) {
                    if (v < bd[k]) {
                        float tf = bd[k]; bd[k] = v;  v  = tf;
                        int   ti = bi[k]; bi[k] = vi; vi = ti;
                    }
                }
            }
        }
#pragma unroll
        for (int k = 0; k < 9; k++) { Pd[tid * 9 + k] = bd[k]; Pi[tid * 9 + k] = bi[k]; }
        __syncthreads();

        // tree merge of sorted 9-lists (double-buffered)
        float* src_d = Pd; float* dst_d = Qd;
        int*   src_i = Pi; int*   dst_i = Qi;
        for (int off = 128; off >= 1; off >>= 1) {
            if (tid < off) {
                const float* Ad = &src_d[tid * 9];
                const int*   Ai = &src_i[tid * 9];
                const float* Bd = &src_d[(tid + off) * 9];
                const int*   Bi = &src_i[(tid + off) * 9];
                float*       Od = &dst_d[tid * 9];
                int*         Oi = &dst_i[tid * 9];
                int ia = 0, ib = 0;
#pragma unroll
                for (int k = 0; k < 9; k++) {
                    float av = Ad[ia], bv = Bd[ib];
                    if (av <= bv) { Od[k] = av; Oi[k] = Ai[ia]; ia++; }
                    else          { Od[k] = bv; Oi[k] = Bi[ib]; ib++; }
                }
            }
            __syncthreads();
            float* td = src_d; src_d = dst_d; dst_d = td;
            int*   ti = src_i; src_i = dst_i; dst_i = ti;
        }
        // after 8 rounds result sits in src_* slots [0,9)
        if (tid < 9) topk_i[lvl * 9 + tid] = src_i[tid];
        __syncthreads();
    }

    // iou + center-inside-gt for the 27 candidates
    if (tid < 27) {
        int a = topk_i[tid];
        float cx, cy, half;
        anchor_geom(a, cx, cy, half);
        float ax0 = cx - half, ay0 = cy - half, ax1 = cx + half, ay1 = cy + half;
        float side = 2.f * half;
        float area_a = side * side;
        iou_s[tid] = iou_eval(ax0, ay0, ax1, ay1, area_a, gx0, gy0, gx1, gy1);
        float l = cx - gx0, t = cy - gy0, r = gx1 - cx, bo = gy1 - cy;
        float mn = fminf(fminf(l, t), fminf(r, bo));
        ok_s[tid] = (mn > EPSV) ? 1 : 0;
    }
    __syncthreads();

    if (tid == 0) {
        float sum = 0.f;
        for (int k = 0; k < 27; k++) sum += iou_s[k];
        float mean = sum / 27.f;
        float ss = 0.f;
        for (int k = 0; k < 27; k++) { float d = iou_s[k] - mean; ss += d * d; }
        thr_s = mean + sqrtf(ss / 26.f);   // std with ddof=1
    }
    __syncthreads();

    if (tid < 27) {
        if (iou_s[tid] > thr_s && ok_s[tid]) {
            int a = topk_i[tid];
            int idx = b * A_VAL + a;
            atomicAdd(&g_pos_count[idx], 1);
            g_pos_gt[idx] = m;   // only consumed when count==1 (single writer then)
        }
    }
}

// ---------------------------------------------------------------------------
// Kernel 2: per (b, anchor) — resolve assignment, write labels (as f32) and
// bboxes. Conflicted anchors (count>1) take argmax_m iou over ALL 64 gts
// (first max), matching the reference's is_max_iou replacement.
// ---------------------------------------------------------------------------
__global__ void __launch_bounds__(256) finalize_kernel(const float* __restrict__ gt_bboxes,
                                                       const int* __restrict__ gt_labels,
                                                       const int* __restrict__ bg_ptr,
                                                       float* __restrict__ out) {
    int idx = blockIdx.x * blockDim.x + threadIdx.x;
    if (idx >= BA_VAL) return;
    int b = idx / A_VAL;
    int a = idx - b * A_VAL;

    int cnt = g_pos_count[idx];
    int gt = 0;
    if (cnt == 1) {
        gt = g_pos_gt[idx];
    } else if (cnt > 1) {
        float cx, cy, half;
        anchor_geom(a, cx, cy, half);
        float ax0 = cx - half, ay0 = cy - half, ax1 = cx + half, ay1 = cy + half;
        float side = 2.f * half;
        float area_a = side * side;
        const float4* gb = reinterpret_cast<const float4*>(gt_bboxes) + b * M_VAL;
        float best = -1.f; int bm = 0;
        for (int mm = 0; mm < M_VAL; mm++) {
            float4 g = __ldg(&gb[mm]);
            float iou = iou_eval(ax0, ay0, ax1, ay1, area_a, g.x, g.y, g.z, g.w);
            if (iou > best) { best = iou; bm = mm; }   // strict > : first max
        }
        gt = bm;
    }

    int label = (cnt > 0) ? gt_labels[b * M_VAL + gt] : __ldg(bg_ptr);
    out[idx] = (float)label;

    float4 g = reinterpret_cast<const float4*>(gt_bboxes)[b * M_VAL + gt];
    reinterpret_cast<float4*>(out + BA_VAL)[idx] = g;   // bboxes region
}

// ---------------------------------------------------------------------------
// Kernel 3: one-hot scores (B*A*80 floats) — pure coalesced float4 writes.
// ---------------------------------------------------------------------------
__global__ void __launch_bounds__(256) scores_kernel(float* __restrict__ out) {
    int i = blockIdx.x * blockDim.x + threadIdx.x;   // float4 index
    const int total4 = BA_VAL * (NC / 4);            // 20 float4 per anchor
    if (i >= total4) return;
    int anchor = i / 20;
    int c0 = (i - anchor * 20) * 4;
    int l = (int)__ldg(out + anchor);                // labels region (just written)
    float4 r;
    r.x = (c0     == l) ? 1.f : 0.f;
    r.y = (c0 + 1 == l) ? 1.f : 0.f;
    r.z = (c0 + 2 == l) ? 1.f : 0.f;
    r.w = (c0 + 3 == l) ? 1.f : 0.f;
    reinterpret_cast<float4*>(out + (size_t)BA_VAL * 5)[i] = r;
}

// ---------------------------------------------------------------------------
extern "C" void kernel_launch(void* const* d_in, const int* in_sizes, int n_in,
                              void* d_out, int out_size) {
    // Locate inputs robustly by element count (metadata order:
    // anchor_bboxes[134400], num_anchors_list[3], gt_labels[1024],
    // gt_bboxes[4096], pad_gt_mask[1024], bg_index[1]).
    const float* gt_bboxes = nullptr;
    const int*   gt_labels = nullptr;
    const float* pad_mask  = nullptr;
    const int*   bg_ptr    = nullptr;
    int seen_1024 = 0;
    for (int i = 0; i < n_in; i++) {
        int sz = in_sizes[i];
        if (sz == BM_VAL * 4)      gt_bboxes = (const float*)d_in[i];
        else if (sz == 1)          bg_ptr    = (const int*)d_in[i];
        else if (sz == BM_VAL) {
            if (seen_1024 == 0) gt_labels = (const int*)d_in[i];   // comes first
            else                pad_mask  = (const float*)d_in[i]; // comes after gt_bboxes
            seen_1024++;
        }
    }
    float* out = (float*)d_out;

    zero_kernel<<<(BA_VAL + 255) / 256, 256>>>();
    topk_assign_kernel<<<BM_VAL, 256>>>(gt_bboxes, pad_mask);
    finalize_kernel<<<(BA_VAL + 255) / 256, 256>>>(gt_bboxes, gt_labels, bg_ptr, out);
    scores_kernel<<<(BA_VAL * (NC / 4) + 255) / 256, 256>>>(out);
}

// round 3
// speedup vs baseline: 1.6863x; 1.6863x over previous
#include <cuda_runtime.h>

#define B_VAL 16
#define M_VAL 64
#define A_VAL 33600
#define BM_VAL (B_VAL * M_VAL)
#define BA_VAL (B_VAL * A_VAL)
#define NC 80
#define EPSV 1e-9f

// Scratch: per-(b,anchor) positive count and (one) contributing gt index.
__device__ int g_pos_count[BA_VAL];
__device__ int g_pos_gt[BA_VAL];

// ---------------------------------------------------------------------------
// Anchor geometry is analytic (exact in f32): level strides 8/16/32,
// grid sides 160/80/40, half-extent 2.5*s.
// ---------------------------------------------------------------------------
__device__ __forceinline__ void anchor_geom(int a, float& cx, float& cy, float& half) {
    int base, nside; float s;
    if (a < 25600)      { s = 8.f;  base = 0;     nside = 160; }
    else if (a < 32000) { s = 16.f; base = 25600; nside = 80;  }
    else                { s = 32.f; base = 32000; nside = 40;  }
    int loc = a - base;
    cx = ((loc % nside) + 0.5f) * s;
    cy = ((loc / nside) + 0.5f) * s;
    half = 2.5f * s;
}

__device__ __forceinline__ float iou_eval(float ax0, float ay0, float ax1, float ay1,
                                          float area_a,
                                          float gx0, float gy0, float gx1, float gy1) {
    float area_g = (gx1 - gx0) * (gy1 - gy0);
    float lx = fmaxf(gx0, ax0), ly = fmaxf(gy0, ay0);
    float rx = fminf(gx1, ax1), ry = fminf(gy1, ay1);
    float w = fmaxf(rx - lx, 0.f), h = fmaxf(ry - ly, 0.f);
    float ov = w * h;
    return ov / (area_g + area_a - ov + EPSV);
}

// ---------------------------------------------------------------------------
// Kernel 0a: zero the scatter counters (graph replays require re-zeroing).
// ---------------------------------------------------------------------------
__global__ void __launch_bounds__(256) zero_counts_kernel() {
    int i = blockIdx.x * blockDim.x + threadIdx.x;   // int4 index
    if (i < BA_VAL / 4) reinterpret_cast<int4*>(g_pos_count)[i] = make_int4(0, 0, 0, 0);
}

// ---------------------------------------------------------------------------
// Kernel 0b: zero the scores region (BA*80 floats = 172MB) with wide stores.
// Each thread writes 4 float4 (64B), consecutive within the warp for fully
// coalesced 128B sectors. Pure-store kernel -> near peak HBM write BW.
// ---------------------------------------------------------------------------
__global__ void __launch_bounds__(256) zero_scores_kernel(float4* __restrict__ p) {
    const int total4 = BA_VAL * (NC / 4);            // 10,752,000 float4
    int i = (blockIdx.x * blockDim.x + threadIdx.x) * 4;
    float4 z = make_float4(0.f, 0.f, 0.f, 0.f);
    if (i + 3 < total4) {
        p[i] = z; p[i + 1] = z; p[i + 2] = z; p[i + 3] = z;
    } else {
        for (int k = i; k < total4; k++) p[k] = z;
    }
}

// ---------------------------------------------------------------------------
// Kernel 1: ONE THREAD per (b, m).
// Top-9 nearest anchors of a level all lie in the clamped 7x7 window around
// the nearest grid node (GT center is within half a cell of the grid, so the
// 3x3 max distance 2.92s < 3.0s lower bound of any node outside +/-3).
// Candidates enumerated in ascending index order with strict-< insertion ==
// jax.lax.top_k lower-index tie-break. Then 27 IoUs, mean+std(ddof=1)
// threshold (same summation order as R1), center-in-gt, atomic scatter.
// ---------------------------------------------------------------------------
__global__ void __launch_bounds__(256) topk_assign_kernel(const float* __restrict__ gt_bboxes,
                                                          const float* __restrict__ pad_mask) {
    const int t = blockIdx.x * blockDim.x + threadIdx.x;   // b*64 + m
    if (t >= BM_VAL) return;
    if (pad_mask[t] <= 0.f) return;

    const int b = t >> 6;
    const int m = t & 63;

    const float4 g = reinterpret_cast<const float4*>(gt_bboxes)[t];
    const float gx0 = g.x, gy0 = g.y, gx1 = g.z, gy1 = g.w;
    const float gcx = (gx0 + gx1) * 0.5f, gcy = (gy0 + gy1) * 0.5f;

    float iou_c[27];
    int   idx_c[27];

#pragma unroll
    for (int lvl = 0; lvl < 3; lvl++) {
        const int   base  = (lvl == 0) ? 0     : (lvl == 1) ? 25600 : 32000;
        const int   nside = (lvl == 0) ? 160   : (lvl == 1) ? 80    : 40;
        const float s     = (lvl == 0) ? 8.f   : (lvl == 1) ? 16.f  : 32.f;
        const float inv_s = (lvl == 0) ? 0.125f : (lvl == 1) ? 0.0625f : 0.03125f;

        int cn = (int)floorf(gcx * inv_s);
        int rn = (int)floorf(gcy * inv_s);
        int c0 = min(max(cn - 3, 0), nside - 7);
        int r0 = min(max(rn - 3, 0), nside - 7);

        float bd[9]; int bi[9];
#pragma unroll
        for (int k = 0; k < 9; k++) { bd[k] = 3.4e38f; bi[k] = 0; }

        for (int r = 0; r < 7; r++) {
            float cy = ((r0 + r) + 0.5f) * s;
            float dy = gcy - cy;
            float dy2 = dy * dy;
            for (int c = 0; c < 7; c++) {
                float cx = ((c0 + c) + 0.5f) * s;
                float dx = gcx - cx;
                float d2 = dx * dx + dy2;
                if (d2 < bd[8]) {
                    float v = d2; int vi = (r0 + r) * nside + (c0 + c);
#pragma unroll
                    for (int k = 0; k < 9; k++) {
                        if (v < bd[k]) {
                            float tf = bd[k]; bd[k] = v;  v  = tf;
                            int   ti = bi[k]; bi[k] = vi; vi = ti;
                        }
                    }
                }
            }
        }

        const float half = 2.5f * s;
        const float area_a = (5.f * s) * (5.f * s);
#pragma unroll
        for (int k = 0; k < 9; k++) {
            int loc = bi[k];
            float cx = ((loc % nside) + 0.5f) * s;
            float cy = ((loc / nside) + 0.5f) * s;
            iou_c[lvl * 9 + k] = iou_eval(cx - half, cy - half, cx + half, cy + half,
                                          area_a, gx0, gy0, gx1, gy1);
            idx_c[lvl * 9 + k] = base + loc;
        }
    }

    // threshold = mean + std(ddof=1) over the 27 candidate ious (same order)
    float sum = 0.f;
#pragma unroll
    for (int k = 0; k < 27; k++) sum += iou_c[k];
    float mean = sum / 27.f;
    float ss = 0.f;
#pragma unroll
    for (int k = 0; k < 27; k++) { float d = iou_c[k] - mean; ss += d * d; }
    float thr = mean + sqrtf(ss / 26.f);

#pragma unroll
    for (int k = 0; k < 27; k++) {
        if (iou_c[k] > thr) {
            int a = idx_c[k];
            float cx, cy, half;
            anchor_geom(a, cx, cy, half);
            float l = cx - gx0, tt = cy - gy0, r = gx1 - cx, bo = gy1 - cy;
            float mn = fminf(fminf(l, tt), fminf(r, bo));
            if (mn > EPSV) {
                int idx = b * A_VAL + a;
                atomicAdd(&g_pos_count[idx], 1);
                g_pos_gt[idx] = m;   // only consumed when count==1 (single writer then)
            }
        }
    }
}

// ---------------------------------------------------------------------------
// Kernel 2: per (b, anchor) — resolve assignment, write labels (f32), bboxes,
// and scatter the single 1.0 into the (pre-zeroed) scores region for
// positive anchors. Conflicted anchors (count>1) take argmax_m iou over ALL
// 64 gts (first max), matching the reference's is_max_iou replacement.
// ---------------------------------------------------------------------------
__global__ void __launch_bounds__(256) finalize_kernel(const float* __restrict__ gt_bboxes,
                                                       const int* __restrict__ gt_labels,
                                                       const int* __restrict__ bg_ptr,
                                                       float* __restrict__ out) {
    int idx = blockIdx.x * blockDim.x + threadIdx.x;
    if (idx >= BA_VAL) return;
    int b = idx / A_VAL;
    int a = idx - b * A_VAL;

    int cnt = g_pos_count[idx];
    int gt = 0;
    if (cnt == 1) {
        gt = g_pos_gt[idx];
    } else if (cnt > 1) {
        float cx, cy, half;
        anchor_geom(a, cx, cy, half);
        float ax0 = cx - half, ay0 = cy - half, ax1 = cx + half, ay1 = cy + half;
        float side = 2.f * half;
        float area_a = side * side;
        const float4* gb = reinterpret_cast<const float4*>(gt_bboxes) + b * M_VAL;
        float best = -1.f; int bm = 0;
        for (int mm = 0; mm < M_VAL; mm++) {
            float4 gg = __ldg(&gb[mm]);
            float iou = iou_eval(ax0, ay0, ax1, ay1, area_a, gg.x, gg.y, gg.z, gg.w);
            if (iou > best) { best = iou; bm = mm; }   // strict > : first max
        }
        gt = bm;
    }

    int label;
    if (cnt > 0) {
        label = gt_labels[b * M_VAL + gt];
        // scores one-hot: region pre-zeroed; positive labels are always < 80
        out[(size_t)BA_VAL * 5 + (size_t)idx * NC + label] = 1.0f;
    } else {
        label = __ldg(bg_ptr);
    }
    out[idx] = (float)label;

    float4 gg = reinterpret_cast<const float4*>(gt_bboxes)[b * M_VAL + gt];
    reinterpret_cast<float4*>(out + BA_VAL)[idx] = gg;   // bboxes region
}

// ---------------------------------------------------------------------------
extern "C" void kernel_launch(void* const* d_in, const int* in_sizes, int n_in,
                              void* d_out, int out_size) {
    const float* gt_bboxes = nullptr;
    const int*   gt_labels = nullptr;
    const float* pad_mask  = nullptr;
    const int*   bg_ptr    = nullptr;
    int seen_1024 = 0;
    for (int i = 0; i < n_in; i++) {
        int sz = in_sizes[i];
        if (sz == BM_VAL * 4)      gt_bboxes = (const float*)d_in[i];
        else if (sz == 1)          bg_ptr    = (const int*)d_in[i];
        else if (sz == BM_VAL) {
            if (seen_1024 == 0) gt_labels = (const int*)d_in[i];   // metadata order
            else                pad_mask  = (const float*)d_in[i];
            seen_1024++;
        }
    }
    float* out = (float*)d_out;

    zero_counts_kernel<<<(BA_VAL / 4 + 255) / 256, 256>>>();

    const int total4 = BA_VAL * (NC / 4);                 // float4 count
    const int threads_needed = (total4 + 3) / 4;          // 4 float4 per thread
    zero_scores_kernel<<<(threads_needed + 255) / 256, 256>>>(
        reinterpret_cast<float4*>(out + (size_t)BA_VAL * 5));

    topk_assign_kernel<<<(BM_VAL + 255) / 256, 256>>>(gt_bboxes, pad_mask);
    finalize_kernel<<<(BA_VAL + 255) / 256, 256>>>(gt_bboxes, gt_labels, bg_ptr, out);
}

// round 4
// speedup vs baseline: 2.1828x; 1.2944x over previous
#include <cuda_runtime.h>

#define B_VAL 16
#define M_VAL 64
#define A_VAL 33600
#define BM_VAL (B_VAL * M_VAL)
#define BA_VAL (B_VAL * A_VAL)
#define NC 80
#define EPSV 1e-9f

// Scratch: per-(b,anchor) positive count and (one) contributing gt index.
__device__ int g_pos_count[BA_VAL];
__device__ int g_pos_gt[BA_VAL];

// ---------------------------------------------------------------------------
__device__ __forceinline__ void anchor_geom(int a, float& cx, float& cy, float& half) {
    int base, nside; float s;
    if (a < 25600)      { s = 8.f;  base = 0;     nside = 160; }
    else if (a < 32000) { s = 16.f; base = 25600; nside = 80;  }
    else                { s = 32.f; base = 32000; nside = 40;  }
    int loc = a - base;
    cx = ((loc % nside) + 0.5f) * s;
    cy = ((loc / nside) + 0.5f) * s;
    half = 2.5f * s;
}

__device__ __forceinline__ float iou_eval(float ax0, float ay0, float ax1, float ay1,
                                          float area_a,
                                          float gx0, float gy0, float gx1, float gy1) {
    float area_g = (gx1 - gx0) * (gy1 - gy0);
    float lx = fmaxf(gx0, ax0), ly = fmaxf(gy0, ay0);
    float rx = fminf(gx1, ax1), ry = fminf(gy1, ay1);
    float w = fmaxf(rx - lx, 0.f), h = fmaxf(ry - ly, 0.f);
    float ov = w * h;
    return ov / (area_g + area_a - ov + EPSV);
}

// ---------------------------------------------------------------------------
// Kernel 0: zero the scatter counters (graph replays require re-zeroing).
// ---------------------------------------------------------------------------
__global__ void __launch_bounds__(256) zero_counts_kernel() {
    int i = blockIdx.x * blockDim.x + threadIdx.x;   // int4 index
    if (i < BA_VAL / 4) reinterpret_cast<int4*>(g_pos_count)[i] = make_int4(0, 0, 0, 0);
}

// ---------------------------------------------------------------------------
// Kernel 1: ONE THREAD per (b, m). Analytic 7x7-window top-9 per level
// (GT center is within half a cell of each grid; 3x3 max dist 2.92s < 3.0s
// lower bound outside +/-3 window). Ascending-index enumeration + strict-<
// insertion == jax.lax.top_k lower-index tie-break. 27 IoUs, mean+std(ddof=1)
// threshold (same summation order), center-in-gt, atomic scatter.
// ---------------------------------------------------------------------------
__global__ void __launch_bounds__(256) topk_assign_kernel(const float* __restrict__ gt_bboxes,
                                                          const float* __restrict__ pad_mask) {
    const int t = blockIdx.x * blockDim.x + threadIdx.x;   // b*64 + m
    if (t >= BM_VAL) return;
    if (pad_mask[t] <= 0.f) return;

    const int b = t >> 6;
    const int m = t & 63;

    const float4 g = reinterpret_cast<const float4*>(gt_bboxes)[t];
    const float gx0 = g.x, gy0 = g.y, gx1 = g.z, gy1 = g.w;
    const float gcx = (gx0 + gx1) * 0.5f, gcy = (gy0 + gy1) * 0.5f;

    float iou_c[27];
    int   idx_c[27];

#pragma unroll
    for (int lvl = 0; lvl < 3; lvl++) {
        const int   base  = (lvl == 0) ? 0     : (lvl == 1) ? 25600 : 32000;
        const int   nside = (lvl == 0) ? 160   : (lvl == 1) ? 80    : 40;
        const float s     = (lvl == 0) ? 8.f   : (lvl == 1) ? 16.f  : 32.f;
        const float inv_s = (lvl == 0) ? 0.125f : (lvl == 1) ? 0.0625f : 0.03125f;

        int cn = (int)floorf(gcx * inv_s);
        int rn = (int)floorf(gcy * inv_s);
        int c0 = min(max(cn - 3, 0), nside - 7);
        int r0 = min(max(rn - 3, 0), nside - 7);

        float bd[9]; int bi[9];
#pragma unroll
        for (int k = 0; k < 9; k++) { bd[k] = 3.4e38f; bi[k] = 0; }

        for (int r = 0; r < 7; r++) {
            float cy = ((r0 + r) + 0.5f) * s;
            float dy = gcy - cy;
            float dy2 = dy * dy;
            for (int c = 0; c < 7; c++) {
                float cx = ((c0 + c) + 0.5f) * s;
                float dx = gcx - cx;
                float d2 = dx * dx + dy2;
                if (d2 < bd[8]) {
                    float v = d2; int vi = (r0 + r) * nside + (c0 + c);
#pragma unroll
                    for (int k = 0; k < 9; k++) {
                        if (v < bd[k]) {
                            float tf = bd[k]; bd[k] = v;  v  = tf;
                            int   ti = bi[k]; bi[k] = vi; vi = ti;
                        }
                    }
                }
            }
        }

        const float half = 2.5f * s;
        const float area_a = (5.f * s) * (5.f * s);
#pragma unroll
        for (int k = 0; k < 9; k++) {
            int loc = bi[k];
            float cx = ((loc % nside) + 0.5f) * s;
            float cy = ((loc / nside) + 0.5f) * s;
            iou_c[lvl * 9 + k] = iou_eval(cx - half, cy - half, cx + half, cy + half,
                                          area_a, gx0, gy0, gx1, gy1);
            idx_c[lvl * 9 + k] = base + loc;
        }
    }

    float sum = 0.f;
#pragma unroll
    for (int k = 0; k < 27; k++) sum += iou_c[k];
    float mean = sum / 27.f;
    float ss = 0.f;
#pragma unroll
    for (int k = 0; k < 27; k++) { float d = iou_c[k] - mean; ss += d * d; }
    float thr = mean + sqrtf(ss / 26.f);

#pragma unroll
    for (int k = 0; k < 27; k++) {
        if (iou_c[k] > thr) {
            int a = idx_c[k];
            float cx, cy, half;
            anchor_geom(a, cx, cy, half);
            float l = cx - gx0, tt = cy - gy0, r = gx1 - cx, bo = gy1 - cy;
            float mn = fminf(fminf(l, tt), fminf(r, bo));
            if (mn > EPSV) {
                int idx = b * A_VAL + a;
                atomicAdd(&g_pos_count[idx], 1);
                g_pos_gt[idx] = m;   // only consumed when count==1 (single writer then)
            }
        }
    }
}

// ---------------------------------------------------------------------------
// Kernel 2 (MEGA): one block per 256 anchors.
//   Phase A: per-thread assignment resolution; write label (f32) + bbox;
//            stash (positive? label : -1) in smem.
//   Phase B: block zeroes its contiguous 256*80-float scores slab with
//            fully unrolled float4 stores (1 STG.128 per 16B -> HBM-bound).
//   Phase C: positive threads scatter their single 1.0f (ordered by sync).
// ---------------------------------------------------------------------------
__global__ void __launch_bounds__(256) mega_kernel(const float* __restrict__ gt_bboxes,
                                                   const int* __restrict__ gt_labels,
                                                   const int* __restrict__ bg_ptr,
                                                   float* __restrict__ out) {
    __shared__ int s_pos_label[256];   // label if positive else -1

    const int tid = threadIdx.x;
    const int idx = blockIdx.x * 256 + tid;          // (b, anchor) flat
    const int b = idx / A_VAL;
    const int a = idx - b * A_VAL;

    // ---- Phase A -----------------------------------------------------------
    int cnt = g_pos_count[idx];
    int gt = 0;
    if (cnt == 1) {
        gt = g_pos_gt[idx];
    } else if (cnt > 1) {
        float cx, cy, half;
        anchor_geom(a, cx, cy, half);
        float ax0 = cx - half, ay0 = cy - half, ax1 = cx + half, ay1 = cy + half;
        float side = 2.f * half;
        float area_a = side * side;
        const float4* gb = reinterpret_cast<const float4*>(gt_bboxes) + b * M_VAL;
        float best = -1.f; int bm = 0;
        for (int mm = 0; mm < M_VAL; mm++) {
            float4 gg = __ldg(&gb[mm]);
            float iou = iou_eval(ax0, ay0, ax1, ay1, area_a, gg.x, gg.y, gg.z, gg.w);
            if (iou > best) { best = iou; bm = mm; }   // strict > : first max
        }
        gt = bm;
    }

    int label;
    if (cnt > 0) {
        label = gt_labels[b * M_VAL + gt];
        s_pos_label[tid] = label;
    } else {
        label = __ldg(bg_ptr);
        s_pos_label[tid] = -1;
    }
    out[idx] = (float)label;

    float4 gg = reinterpret_cast<const float4*>(gt_bboxes)[b * M_VAL + gt];
    reinterpret_cast<float4*>(out + BA_VAL)[idx] = gg;   // bboxes region

    // ---- Phase B: zero this block's scores slab ---------------------------
    // slab: 256 anchors * 80 floats = 5120 float4, contiguous.
    float4* slab = reinterpret_cast<float4*>(out + (size_t)BA_VAL * 5) +
                   (size_t)blockIdx.x * 256 * (NC / 4);
    const float4 z = make_float4(0.f, 0.f, 0.f, 0.f);
#pragma unroll
    for (int j = 0; j < 20; j++) {
        slab[j * 256 + tid] = z;
    }

    __syncthreads();

    // ---- Phase C: scatter sparse 1.0s -------------------------------------
    int pl = s_pos_label[tid];
    if (pl >= 0) {
        reinterpret_cast<float*>(slab)[tid * NC + pl] = 1.0f;
    }
}

// ---------------------------------------------------------------------------
extern "C" void kernel_launch(void* const* d_in, const int* in_sizes, int n_in,
                              void* d_out, int out_size) {
    const float* gt_bboxes = nullptr;
    const int*   gt_labels = nullptr;
    const float* pad_mask  = nullptr;
    const int*   bg_ptr    = nullptr;
    int seen_1024 = 0;
    for (int i = 0; i < n_in; i++) {
        int sz = in_sizes[i];
        if (sz == BM_VAL * 4)      gt_bboxes = (const float*)d_in[i];
        else if (sz == 1)          bg_ptr    = (const int*)d_in[i];
        else if (sz == BM_VAL) {
            if (seen_1024 == 0) gt_labels = (const int*)d_in[i];   // metadata order
            else                pad_mask  = (const float*)d_in[i];
            seen_1024++;
        }
    }
    float* out = (float*)d_out;

    zero_counts_kernel<<<(BA_VAL / 4 + 255) / 256, 256>>>();
    topk_assign_kernel<<<(BM_VAL + 255) / 256, 256>>>(gt_bboxes, pad_mask);
    mega_kernel<<<BA_VAL / 256, 256>>>(gt_bboxes, gt_labels, bg_ptr, out);
}

// round 5
// speedup vs baseline: 2.3180x; 1.0620x over previous
#include <cuda_runtime.h>

#define B_VAL 16
#define M_VAL 64
#define A_VAL 33600
#define BM_VAL (B_VAL * M_VAL)
#define BA_VAL (B_VAL * A_VAL)
#define NC 80
#define EPSV 1e-9f

// Scratch: per-(b,anchor) positive count and (one) contributing gt index.
// Zero-initialized at module load; mega_kernel self-cleans g_pos_count after
// reading, so every launch (and graph replay) begins with a zeroed table.
__device__ int g_pos_count[BA_VAL];
__device__ int g_pos_gt[BA_VAL];

// ---------------------------------------------------------------------------
__device__ __forceinline__ void anchor_geom(int a, float& cx, float& cy, float& half) {
    int base, nside; float s;
    if (a < 25600)      { s = 8.f;  base = 0;     nside = 160; }
    else if (a < 32000) { s = 16.f; base = 25600; nside = 80;  }
    else                { s = 32.f; base = 32000; nside = 40;  }
    int loc = a - base;
    cx = ((loc % nside) + 0.5f) * s;
    cy = ((loc / nside) + 0.5f) * s;
    half = 2.5f * s;
}

__device__ __forceinline__ float iou_eval(float ax0, float ay0, float ax1, float ay1,
                                          float area_a,
                                          float gx0, float gy0, float gx1, float gy1) {
    float area_g = (gx1 - gx0) * (gy1 - gy0);
    float lx = fmaxf(gx0, ax0), ly = fmaxf(gy0, ay0);
    float rx = fminf(gx1, ax1), ry = fminf(gy1, ay1);
    float w = fmaxf(rx - lx, 0.f), h = fmaxf(ry - ly, 0.f);
    float ov = w * h;
    return ov / (area_g + area_a - ov + EPSV);
}

// ---------------------------------------------------------------------------
// Kernel 1: ONE THREAD per (b, m). Analytic 7x7-window top-9 per level
// (GT center is within half a cell of each grid; 3x3 max dist 2.92s < 3.0s
// lower bound outside +/-3 window). Ascending-index enumeration + strict-<
// insertion == jax.lax.top_k lower-index tie-break. 27 IoUs, mean+std(ddof=1)
// threshold (same summation order), center-in-gt, atomic scatter.
// ---------------------------------------------------------------------------
__global__ void __launch_bounds__(256) topk_assign_kernel(const float* __restrict__ gt_bboxes,
                                                          const float* __restrict__ pad_mask) {
    const int t = blockIdx.x * blockDim.x + threadIdx.x;   // b*64 + m
    if (t >= BM_VAL) return;
    if (pad_mask[t] <= 0.f) return;

    const int b = t >> 6;
    const int m = t & 63;

    const float4 g = reinterpret_cast<const float4*>(gt_bboxes)[t];
    const float gx0 = g.x, gy0 = g.y, gx1 = g.z, gy1 = g.w;
    const float gcx = (gx0 + gx1) * 0.5f, gcy = (gy0 + gy1) * 0.5f;

    float iou_c[27];
    int   idx_c[27];

#pragma unroll
    for (int lvl = 0; lvl < 3; lvl++) {
        const int   base  = (lvl == 0) ? 0     : (lvl == 1) ? 25600 : 32000;
        const int   nside = (lvl == 0) ? 160   : (lvl == 1) ? 80    : 40;
        const float s     = (lvl == 0) ? 8.f   : (lvl == 1) ? 16.f  : 32.f;
        const float inv_s = (lvl == 0) ? 0.125f : (lvl == 1) ? 0.0625f : 0.03125f;

        int cn = (int)floorf(gcx * inv_s);
        int rn = (int)floorf(gcy * inv_s);
        int c0 = min(max(cn - 3, 0), nside - 7);
        int r0 = min(max(rn - 3, 0), nside - 7);

        float bd[9]; int bi[9];
#pragma unroll
        for (int k = 0; k < 9; k++) { bd[k] = 3.4e38f; bi[k] = 0; }

        for (int r = 0; r < 7; r++) {
            float cy = ((r0 + r) + 0.5f) * s;
            float dy = gcy - cy;
            float dy2 = dy * dy;
            for (int c = 0; c < 7; c++) {
                float cx = ((c0 + c) + 0.5f) * s;
                float dx = gcx - cx;
                float d2 = dx * dx + dy2;
                if (d2 < bd[8]) {
                    float v = d2; int vi = (r0 + r) * nside + (c0 + c);
#pragma unroll
                    for (int k = 0; k < 9; k++) {
                        if (v < bd[k]) {
                            float tf = bd[k]; bd[k] = v;  v  = tf;
                            int   ti = bi[k]; bi[k] = vi; vi = ti;
                        }
                    }
                }
            }
        }

        const float half = 2.5f * s;
        const float area_a = (5.f * s) * (5.f * s);
#pragma unroll
        for (int k = 0; k < 9; k++) {
            int loc = bi[k];
            float cx = ((loc % nside) + 0.5f) * s;
            float cy = ((loc / nside) + 0.5f) * s;
            iou_c[lvl * 9 + k] = iou_eval(cx - half, cy - half, cx + half, cy + half,
                                          area_a, gx0, gy0, gx1, gy1);
            idx_c[lvl * 9 + k] = base + loc;
        }
    }

    float sum = 0.f;
#pragma unroll
    for (int k = 0; k < 27; k++) sum += iou_c[k];
    float mean = sum / 27.f;
    float ss = 0.f;
#pragma unroll
    for (int k = 0; k < 27; k++) { float d = iou_c[k] - mean; ss += d * d; }
    float thr = mean + sqrtf(ss / 26.f);

#pragma unroll
    for (int k = 0; k < 27; k++) {
        if (iou_c[k] > thr) {
            int a = idx_c[k];
            float cx, cy, half;
            anchor_geom(a, cx, cy, half);
            float l = cx - gx0, tt = cy - gy0, r = gx1 - cx, bo = gy1 - cy;
            float mn = fminf(fminf(l, tt), fminf(r, bo));
            if (mn > EPSV) {
                int idx = b * A_VAL + a;
                atomicAdd(&g_pos_count[idx], 1);
                g_pos_gt[idx] = m;   // only consumed when count==1 (single writer then)
            }
        }
    }
}

// ---------------------------------------------------------------------------
// Kernel 2 (MEGA): one block per 256 anchors.
//   Phase A: per-thread assignment resolution (then SELF-CLEAN the counter
//            for the next graph replay); write label (f32) + bbox; stash
//            (positive? label : -1) in smem.
//   Phase B: block zeroes its contiguous 256*80-float scores slab with
//            streaming float4 stores (write-once data: evict-first).
//   Phase C: positive threads scatter their single 1.0f (ordered by sync).
// ---------------------------------------------------------------------------
__global__ void __launch_bounds__(256) mega_kernel(const float* __restrict__ gt_bboxes,
                                                   const int* __restrict__ gt_labels,
                                                   const int* __restrict__ bg_ptr,
                                                   float* __restrict__ out) {
    __shared__ int s_pos_label[256];   // label if positive else -1

    const int tid = threadIdx.x;
    const int idx = blockIdx.x * 256 + tid;          // (b, anchor) flat
    const int b = idx / A_VAL;
    const int a = idx - b * A_VAL;

    // ---- Phase A -----------------------------------------------------------
    int cnt = g_pos_count[idx];
    if (cnt != 0) g_pos_count[idx] = 0;              // self-clean for next launch
    int gt = 0;
    if (cnt == 1) {
        gt = g_pos_gt[idx];
    } else if (cnt > 1) {
        float cx, cy, half;
        anchor_geom(a, cx, cy, half);
        float ax0 = cx - half, ay0 = cy - half, ax1 = cx + half, ay1 = cy + half;
        float side = 2.f * half;
        float area_a = side * side;
        const float4* gb = reinterpret_cast<const float4*>(gt_bboxes) + b * M_VAL;
        float best = -1.f; int bm = 0;
        for (int mm = 0; mm < M_VAL; mm++) {
            float4 gg = __ldg(&gb[mm]);
            float iou = iou_eval(ax0, ay0, ax1, ay1, area_a, gg.x, gg.y, gg.z, gg.w);
            if (iou > best) { best = iou; bm = mm; }   // strict > : first max
        }
        gt = bm;
    }

    int label;
    if (cnt > 0) {
        label = gt_labels[b * M_VAL + gt];
        s_pos_label[tid] = label;
    } else {
        label = __ldg(bg_ptr);
        s_pos_label[tid] = -1;
    }
    __stcs(out + idx, (float)label);

    float4 gg = reinterpret_cast<const float4*>(gt_bboxes)[b * M_VAL + gt];
    __stcs(reinterpret_cast<float4*>(out + BA_VAL) + idx, gg);   // bboxes region

    // ---- Phase B: zero this block's scores slab (streaming stores) --------
    // slab: 256 anchors * 80 floats = 5120 float4, contiguous.
    float4* slab = reinterpret_cast<float4*>(out + (size_t)BA_VAL * 5) +
                   (size_t)blockIdx.x * 256 * (NC / 4);
    const float4 z = make_float4(0.f, 0.f, 0.f, 0.f);
#pragma unroll
    for (int j = 0; j < 20; j++) {
        __stcs(slab + j * 256 + tid, z);
    }

    __syncthreads();

    // ---- Phase C: scatter sparse 1.0s -------------------------------------
    int pl = s_pos_label[tid];
    if (pl >= 0) {
        reinterpret_cast<float*>(slab)[tid * NC + pl] = 1.0f;
    }
}

// ---------------------------------------------------------------------------
extern "C" void kernel_launch(void* const* d_in, const int* in_sizes, int n_in,
                              void* d_out, int out_size) {
    const float* gt_bboxes = nullptr;
    const int*   gt_labels = nullptr;
    const float* pad_mask  = nullptr;
    const int*   bg_ptr    = nullptr;
    int seen_1024 = 0;
    for (int i = 0; i < n_in; i++) {
        int sz = in_sizes[i];
        if (sz == BM_VAL * 4)      gt_bboxes = (const float*)d_in[i];
        else if (sz == 1)          bg_ptr    = (const int*)d_in[i];
        else if (sz == BM_VAL) {
            if (seen_1024 == 0) gt_labels = (const int*)d_in[i];   // metadata order
            else                pad_mask  = (const float*)d_in[i];
            seen_1024++;
        }
    }
    float* out = (float*)d_out;

    topk_assign_kernel<<<(BM_VAL + 255) / 256, 256>>>(gt_bboxes, pad_mask);
    mega_kernel<<<BA_VAL / 256, 256>>>(gt_bboxes, gt_labels, bg_ptr, out);
}